// round 1
// baseline (speedup 1.0000x reference)
#include <cuda_runtime.h>
#include <cstdint>

// ---------------------------------------------------------------------------
// Problem constants (fixed shapes per reference)
// ---------------------------------------------------------------------------
#define DNF 100000
#define DNA 400
#define DNC 30
#define DNT (DNF + DNA + DNC)   // 100430 total nodes
#define DD  256                 // hidden channels
#define DE  250000              // edges per relation
#define DB  3                   // bases
#define DR  4                   // relations

// ---------------------------------------------------------------------------
// Device scratch (no allocations allowed)
// ---------------------------------------------------------------------------
__device__ __align__(16) float g_A[(size_t)DNT * DD];     // buffer A (node feats)
__device__ __align__(16) float g_Bf[(size_t)DNT * DD];    // buffer B (layer out)
__device__ __align__(16) float g_W[2][DR][DD * DD];       // per-layer relation weights
__device__ __align__(16) float g_Y1[DNA * DD];            // airport msgs (rel1)
__device__ __align__(16) float g_Y3[DNC * DD];            // carrier msgs (rel3)
__device__ __align__(16) float g_S0[DNA * DD];            // rel0 aggregate
__device__ __align__(16) float g_S2[DNC * DD];            // rel2 aggregate
__device__ int   g_deg0[DNA];
__device__ int   g_deg1[DNF];
__device__ int   g_deg2[DNC];
__device__ int   g_deg3[DNF];
__device__ float g_inv1[DNF];
__device__ float g_inv3[DNF];

// ---------------------------------------------------------------------------
// Small utility kernels
// ---------------------------------------------------------------------------
__global__ void zero_f_kernel(float* p, int n) {
    for (int i = blockIdx.x * blockDim.x + threadIdx.x; i < n;
         i += gridDim.x * blockDim.x)
        p[i] = 0.0f;
}

__global__ void zero_i_kernel(int* p, int n) {
    for (int i = blockIdx.x * blockDim.x + threadIdx.x; i < n;
         i += gridDim.x * blockDim.x)
        p[i] = 0;
}

__global__ void relu_kernel(float* p, int n) {
    for (int i = blockIdx.x * blockDim.x + threadIdx.x; i < n;
         i += gridDim.x * blockDim.x)
        p[i] = fmaxf(p[i], 0.0f);
}

// W[r] = sum_b comp[r,b] * basis[b]
__global__ void compute_W_kernel(const float* __restrict__ basis,
                                 const float* __restrict__ comp,
                                 float* __restrict__ Wout) {
    int idx = blockIdx.x * blockDim.x + threadIdx.x;
    int total = DR * DD * DD;
    if (idx >= total) return;
    int r  = idx / (DD * DD);
    int io = idx % (DD * DD);
    float acc = 0.0f;
#pragma unroll
    for (int b = 0; b < DB; b++)
        acc += comp[r * DB + b] * basis[(size_t)b * DD * DD + io];
    Wout[idx] = acc;
}

__global__ void count_deg_kernel(const int* __restrict__ dst, int* deg, int E) {
    for (int i = blockIdx.x * blockDim.x + threadIdx.x; i < E;
         i += gridDim.x * blockDim.x)
        atomicAdd(&deg[dst[i]], 1);
}

__global__ void make_inv_kernel(const int* __restrict__ deg, float* inv, int n) {
    for (int i = blockIdx.x * blockDim.x + threadIdx.x; i < n;
         i += gridDim.x * blockDim.x)
        inv[i] = 1.0f / (float)max(deg[i], 1);
}

// S[row][:] /= max(deg[row],1)
__global__ void norm_rows_kernel(float* S, const int* __restrict__ deg, int rows) {
    int idx = blockIdx.x * blockDim.x + threadIdx.x;
    int n = rows * DD;
    if (idx >= n) return;
    int r = idx / DD;
    S[idx] *= 1.0f / (float)max(deg[r], 1);
}

// ---------------------------------------------------------------------------
// Type encoders: out[row] = relu(x[row] @ W + b), 32 rows per block, 256 threads
// ---------------------------------------------------------------------------
template <int K>
__global__ void encode_kernel(const float* __restrict__ X,
                              const float* __restrict__ W,
                              const float* __restrict__ bias,
                              float* __restrict__ out, int M) {
    __shared__ float Ws[K * DD];
    __shared__ float Xs[32 * K];
    int tid = threadIdx.x;
    for (int i = tid; i < K * DD; i += 256) Ws[i] = W[i];
    int r0 = blockIdx.x * 32;
    int rows = min(32, M - r0);
    for (int i = tid; i < rows * K; i += 256) Xs[i] = X[(size_t)r0 * K + i];
    __syncthreads();
    int col = tid;
    float bv = bias[col];
    for (int row = 0; row < rows; row++) {
        float acc = 0.0f;
#pragma unroll
        for (int k = 0; k < K; k++) acc += Xs[row * K + k] * Ws[k * DD + col];
        out[(size_t)(r0 + row) * DD + col] = fmaxf(acc + bv, 0.0f);
    }
}

// ---------------------------------------------------------------------------
// fp32 SGEMM: C[M x 256] = A[M x 256] @ Bw[256 x 256] (+ bias | += C)
// 128x128 blocktile, BK=8, 8x8 per thread, 256 threads.
// ---------------------------------------------------------------------------
#define BM 128
#define BN 128
#define BK 8

__global__ void __launch_bounds__(256, 2)
gemm256_kernel(const float* __restrict__ A, const float* __restrict__ Bw,
               const float* __restrict__ bias, float* __restrict__ C,
               int M, int accum) {
    __shared__ float As[BK][BM];
    __shared__ float Bs[BK][BN];

    int tid = threadIdx.x;
    int rowBase = blockIdx.x * BM;
    int colBase = blockIdx.y * BN;
    int tx = tid & 15;        // 0..15
    int ty = tid >> 4;        // 0..15

    int aRow = tid >> 1;          // 0..127
    int aCol = (tid & 1) * 4;     // 0 or 4
    int bRow = tid >> 5;          // 0..7
    int bCol = (tid & 31) * 4;    // 0..124

    float acc[8][8];
#pragma unroll
    for (int i = 0; i < 8; i++)
#pragma unroll
        for (int j = 0; j < 8; j++) acc[i][j] = 0.0f;

    for (int k0 = 0; k0 < DD; k0 += BK) {
        float4 av = make_float4(0.f, 0.f, 0.f, 0.f);
        int ar = rowBase + aRow;
        if (ar < M)
            av = *(const float4*)(A + (size_t)ar * DD + k0 + aCol);
        As[aCol + 0][aRow] = av.x;
        As[aCol + 1][aRow] = av.y;
        As[aCol + 2][aRow] = av.z;
        As[aCol + 3][aRow] = av.w;

        float4 bv = *(const float4*)(Bw + (size_t)(k0 + bRow) * DD + colBase + bCol);
        *(float4*)(&Bs[bRow][bCol]) = bv;
        __syncthreads();

#pragma unroll
        for (int kk = 0; kk < BK; kk++) {
            float ra[8], rb[8];
#pragma unroll
            for (int i = 0; i < 8; i++) ra[i] = As[kk][ty * 8 + i];
#pragma unroll
            for (int j = 0; j < 8; j++) rb[j] = Bs[kk][tx * 8 + j];
#pragma unroll
            for (int i = 0; i < 8; i++)
#pragma unroll
                for (int j = 0; j < 8; j++) acc[i][j] += ra[i] * rb[j];
        }
        __syncthreads();
    }

#pragma unroll
    for (int i = 0; i < 8; i++) {
        int row = rowBase + ty * 8 + i;
        if (row >= M) continue;
#pragma unroll
        for (int j4 = 0; j4 < 8; j4 += 4) {
            int col = colBase + tx * 8 + j4;
            float4 v = make_float4(acc[i][j4], acc[i][j4 + 1],
                                   acc[i][j4 + 2], acc[i][j4 + 3]);
            float* cp = C + (size_t)row * DD + col;
            if (accum) {
                float4 o = *(const float4*)cp;
                v.x += o.x; v.y += o.y; v.z += o.z; v.w += o.w;
            } else if (bias) {
                v.x += bias[col];     v.y += bias[col + 1];
                v.z += bias[col + 2]; v.w += bias[col + 3];
            }
            *(float4*)cp = v;
        }
    }
}

// ---------------------------------------------------------------------------
// Edge scatter: out[dst[e]] += tab[src[e]] * (inv ? inv[dst[e]] : 1)
// one warp per edge; red.global.add.v4.f32 (sm_90+)
// ---------------------------------------------------------------------------
__device__ __forceinline__ void red_add_v4(float* addr, float4 v) {
    asm volatile("red.global.add.v4.f32 [%0], {%1,%2,%3,%4};"
                 :: "l"(addr), "f"(v.x), "f"(v.y), "f"(v.z), "f"(v.w)
                 : "memory");
}

__global__ void scatter_add_kernel(const float* __restrict__ tab,
                                   const int* __restrict__ src,
                                   const int* __restrict__ dst,
                                   const float* __restrict__ inv,
                                   float* __restrict__ out, int E) {
    int w = (blockIdx.x * blockDim.x + threadIdx.x) >> 5;
    int lane = threadIdx.x & 31;
    if (w >= E) return;
    int s = src[w];
    int d = dst[w];
    float sc = inv ? inv[d] : 1.0f;
    const float4* in4 = (const float4*)(tab + (size_t)s * DD);
    float4 a = in4[lane];
    float4 b = in4[lane + 32];
    a.x *= sc; a.y *= sc; a.z *= sc; a.w *= sc;
    b.x *= sc; b.y *= sc; b.z *= sc; b.w *= sc;
    float* ob = out + (size_t)d * DD;
    red_add_v4(ob + lane * 4, a);
    red_add_v4(ob + (lane + 32) * 4, b);
}

// ---------------------------------------------------------------------------
// Readout: out[row] = x[row] . W_out + b_out, warp per row
// ---------------------------------------------------------------------------
__global__ void readout_kernel(const float* __restrict__ X,
                               const float* __restrict__ Wout,
                               const float* __restrict__ bout,
                               float* __restrict__ out, int M) {
    int w = (blockIdx.x * blockDim.x + threadIdx.x) >> 5;
    int lane = threadIdx.x & 31;
    if (w >= M) return;
    const float4* x4 = (const float4*)(X + (size_t)w * DD);
    const float4* w4 = (const float4*)Wout;
    float4 a = x4[lane],     wa = w4[lane];
    float4 b = x4[lane + 32], wb = w4[lane + 32];
    float s = a.x * wa.x + a.y * wa.y + a.z * wa.z + a.w * wa.w
            + b.x * wb.x + b.y * wb.y + b.z * wb.z + b.w * wb.w;
#pragma unroll
    for (int off = 16; off > 0; off >>= 1)
        s += __shfl_down_sync(0xffffffffu, s, off);
    if (lane == 0) out[w] = s + bout[0];
}

// ---------------------------------------------------------------------------
// Launch
// ---------------------------------------------------------------------------
extern "C" void kernel_launch(void* const* d_in, const int* in_sizes, int n_in,
                              void* d_out, int out_size) {
    (void)in_sizes; (void)n_in; (void)out_size;

    const float* x_flight  = (const float*)d_in[0];
    const float* x_airport = (const float*)d_in[1];
    const float* x_carrier = (const float*)d_in[2];
    const float* W_f = (const float*)d_in[3];
    const float* b_f = (const float*)d_in[4];
    const float* W_a = (const float*)d_in[5];
    const float* b_a = (const float*)d_in[6];
    const float* W_c = (const float*)d_in[7];
    const float* b_c = (const float*)d_in[8];
    const float* basis0 = (const float*)d_in[9];
    const float* comp0  = (const float*)d_in[10];
    const float* root0  = (const float*)d_in[11];
    const float* bias0  = (const float*)d_in[12];
    const float* basis1 = (const float*)d_in[13];
    const float* comp1  = (const float*)d_in[14];
    const float* root1  = (const float*)d_in[15];
    const float* bias1  = (const float*)d_in[16];
    const float* W_out  = (const float*)d_in[17];
    const float* b_out  = (const float*)d_in[18];
    const int* src0 = (const int*)d_in[19];
    const int* dst0 = (const int*)d_in[20];
    const int* src1 = (const int*)d_in[21];
    const int* dst1 = (const int*)d_in[22];
    const int* src2 = (const int*)d_in[23];
    const int* dst2 = (const int*)d_in[24];
    const int* src3 = (const int*)d_in[25];
    const int* dst3 = (const int*)d_in[26];
    float* out_final = (float*)d_out;

    void *pA, *pB, *pW, *pY1, *pY3, *pS0, *pS2;
    void *pd0, *pd1, *pd2, *pd3, *pi1, *pi3;
    cudaGetSymbolAddress(&pA,  g_A);
    cudaGetSymbolAddress(&pB,  g_Bf);
    cudaGetSymbolAddress(&pW,  g_W);
    cudaGetSymbolAddress(&pY1, g_Y1);
    cudaGetSymbolAddress(&pY3, g_Y3);
    cudaGetSymbolAddress(&pS0, g_S0);
    cudaGetSymbolAddress(&pS2, g_S2);
    cudaGetSymbolAddress(&pd0, g_deg0);
    cudaGetSymbolAddress(&pd1, g_deg1);
    cudaGetSymbolAddress(&pd2, g_deg2);
    cudaGetSymbolAddress(&pd3, g_deg3);
    cudaGetSymbolAddress(&pi1, g_inv1);
    cudaGetSymbolAddress(&pi3, g_inv3);

    float* A  = (float*)pA;
    float* Bf = (float*)pB;
    float* W  = (float*)pW;         // [2][4][256*256]
    float* Y1 = (float*)pY1;
    float* Y3 = (float*)pY3;
    float* S0 = (float*)pS0;
    float* S2 = (float*)pS2;
    int* deg0 = (int*)pd0;
    int* deg1 = (int*)pd1;
    int* deg2 = (int*)pd2;
    int* deg3 = (int*)pd3;
    float* inv1 = (float*)pi1;
    float* inv3 = (float*)pi3;

    const size_t WSZ = (size_t)DD * DD;  // 65536
    float* W0 = W;                       // layer 0 relation weights
    float* W1 = W + DR * WSZ;            // layer 1 relation weights

    // 1. relation weights from basis decomposition (both layers)
    {
        int total = DR * DD * DD;
        int blocks = (total + 255) / 256;
        compute_W_kernel<<<blocks, 256>>>(basis0, comp0, W0);
        compute_W_kernel<<<blocks, 256>>>(basis1, comp1, W1);
    }

    // 2. encoders -> A
    encode_kernel<32><<<(DNF + 31) / 32, 256>>>(x_flight, W_f, b_f, A, DNF);
    encode_kernel<16><<<(DNA + 31) / 32, 256>>>(x_airport, W_a, b_a,
                                                A + (size_t)DNF * DD, DNA);
    encode_kernel<8><<<(DNC + 31) / 32, 256>>>(x_carrier, W_c, b_c,
                                               A + (size_t)(DNF + DNA) * DD, DNC);

    // 3. degrees + inverse degrees (shared across both layers)
    zero_i_kernel<<<64, 256>>>(deg0, DNA);
    zero_i_kernel<<<512, 256>>>(deg1, DNF);
    zero_i_kernel<<<64, 256>>>(deg2, DNC);
    zero_i_kernel<<<512, 256>>>(deg3, DNF);
    {
        int blocks = (DE + 255) / 256;
        count_deg_kernel<<<blocks, 256>>>(dst0, deg0, DE);
        count_deg_kernel<<<blocks, 256>>>(dst1, deg1, DE);
        count_deg_kernel<<<blocks, 256>>>(dst2, deg2, DE);
        count_deg_kernel<<<blocks, 256>>>(dst3, deg3, DE);
    }
    make_inv_kernel<<<(DNF + 255) / 256, 256>>>(deg1, inv1, DNF);
    make_inv_kernel<<<(DNF + 255) / 256, 256>>>(deg3, inv3, DNF);

    const int scatterBlocks = (DE * 32 + 255) / 256;
    dim3 gemmFullGrid((DNT + BM - 1) / BM, 2);
    dim3 gemmNFGrid((DNF + BM - 1) / BM, 2);
    dim3 gemmNAGrid((DNA + BM - 1) / BM, 2);
    dim3 gemmNCGrid((DNC + BM - 1) / BM, 2);

    // -------------------- Layer 0 --------------------
    // root/self transform over all nodes: Bf = A @ root0 + bias0
    gemm256_kernel<<<gemmFullGrid, 256>>>(A, root0, bias0, Bf, DNT, 0);

    // messages for airport->flight and carrier->flight (tiny GEMMs first)
    gemm256_kernel<<<gemmNAGrid, 256>>>(A + (size_t)DNF * DD, W0 + 1 * WSZ,
                                        nullptr, Y1, DNA, 0);
    gemm256_kernel<<<gemmNCGrid, 256>>>(A + (size_t)(DNF + DNA) * DD, W0 + 3 * WSZ,
                                        nullptr, Y3, DNC, 0);

    // rel0 / rel2 aggregates (aggregate raw x, GEMM after)
    zero_f_kernel<<<256, 256>>>(S0, DNA * DD);
    zero_f_kernel<<<64, 256>>>(S2, DNC * DD);
    scatter_add_kernel<<<scatterBlocks, 256>>>(A, src0, dst0, nullptr, S0, DE);
    scatter_add_kernel<<<scatterBlocks, 256>>>(A, src2, dst2, nullptr, S2, DE);
    norm_rows_kernel<<<(DNA * DD + 255) / 256, 256>>>(S0, deg0, DNA);
    norm_rows_kernel<<<(DNC * DD + 255) / 256, 256>>>(S2, deg2, DNC);
    gemm256_kernel<<<gemmNAGrid, 256>>>(S0, W0 + 0 * WSZ, nullptr,
                                        Bf + (size_t)DNF * DD, DNA, 1);
    gemm256_kernel<<<gemmNCGrid, 256>>>(S2, W0 + 2 * WSZ, nullptr,
                                        Bf + (size_t)(DNF + DNA) * DD, DNC, 1);

    // rel1 / rel3 scatter (pre-GEMMed messages) into flight rows of Bf
    scatter_add_kernel<<<scatterBlocks, 256>>>(Y1, src1, dst1, inv1, Bf, DE);
    scatter_add_kernel<<<scatterBlocks, 256>>>(Y3, src3, dst3, inv3, Bf, DE);

    relu_kernel<<<4096, 256>>>(Bf, DNT * DD);

    // -------------------- Layer 1 (flight rows only needed) --------------------
    gemm256_kernel<<<gemmNFGrid, 256>>>(Bf, root1, bias1, A, DNF, 0);
    gemm256_kernel<<<gemmNAGrid, 256>>>(Bf + (size_t)DNF * DD, W1 + 1 * WSZ,
                                        nullptr, Y1, DNA, 0);
    gemm256_kernel<<<gemmNCGrid, 256>>>(Bf + (size_t)(DNF + DNA) * DD, W1 + 3 * WSZ,
                                        nullptr, Y3, DNC, 0);
    scatter_add_kernel<<<scatterBlocks, 256>>>(Y1, src1, dst1, inv1, A, DE);
    scatter_add_kernel<<<scatterBlocks, 256>>>(Y3, src3, dst3, inv3, A, DE);
    relu_kernel<<<4096, 256>>>(A, DNF * DD);

    // -------------------- Readout --------------------
    readout_kernel<<<(DNF * 32 + 255) / 256, 256>>>(A, W_out, b_out,
                                                    out_final, DNF);
}

// round 2
// speedup vs baseline: 1.0011x; 1.0011x over previous
#include <cuda_runtime.h>
#include <cstdint>

// ---------------------------------------------------------------------------
// Problem constants (fixed shapes per reference)
// ---------------------------------------------------------------------------
#define DNF 100000
#define DNA 400
#define DNC 30
#define DNT (DNF + DNA + DNC)   // 100430 total nodes
#define DD  256                 // hidden channels
#define DE  250000              // edges per relation
#define DB  3                   // bases
#define DR  4                   // relations

// ---------------------------------------------------------------------------
// Device scratch (no allocations allowed)
// ---------------------------------------------------------------------------
__device__ __align__(16) float g_A[(size_t)DNT * DD];     // buffer A (node feats)
__device__ __align__(16) float g_Bf[(size_t)DNT * DD];    // buffer B (layer out)
__device__ __align__(16) float g_W[2][DR][DD * DD];       // per-layer relation weights
__device__ __align__(16) float g_Y1[DNA * DD];            // airport msgs (rel1)
__device__ __align__(16) float g_Y3[DNC * DD];            // carrier msgs (rel3)
__device__ __align__(16) float g_S0[DNA * DD];            // rel0 aggregate
__device__ __align__(16) float g_S2[DNC * DD];            // rel2 aggregate
__device__ int   g_deg0[DNA];
__device__ int   g_deg1[DNF];
__device__ int   g_deg2[DNC];
__device__ int   g_deg3[DNF];
__device__ float g_inv1[DNF];
__device__ float g_inv3[DNF];

// ---------------------------------------------------------------------------
// Small utility kernels
// ---------------------------------------------------------------------------
__global__ void zero_f_kernel(float* p, int n) {
    for (int i = blockIdx.x * blockDim.x + threadIdx.x; i < n;
         i += gridDim.x * blockDim.x)
        p[i] = 0.0f;
}

__global__ void zero_i_kernel(int* p, int n) {
    for (int i = blockIdx.x * blockDim.x + threadIdx.x; i < n;
         i += gridDim.x * blockDim.x)
        p[i] = 0;
}

__global__ void relu_kernel(float* p, int n) {
    for (int i = blockIdx.x * blockDim.x + threadIdx.x; i < n;
         i += gridDim.x * blockDim.x)
        p[i] = fmaxf(p[i], 0.0f);
}

// W[r] = sum_b comp[r,b] * basis[b]
__global__ void compute_W_kernel(const float* __restrict__ basis,
                                 const float* __restrict__ comp,
                                 float* __restrict__ Wout) {
    int idx = blockIdx.x * blockDim.x + threadIdx.x;
    int total = DR * DD * DD;
    if (idx >= total) return;
    int r  = idx / (DD * DD);
    int io = idx % (DD * DD);
    float acc = 0.0f;
#pragma unroll
    for (int b = 0; b < DB; b++)
        acc += comp[r * DB + b] * basis[(size_t)b * DD * DD + io];
    Wout[idx] = acc;
}

__global__ void count_deg_kernel(const int* __restrict__ dst, int* deg, int E) {
    for (int i = blockIdx.x * blockDim.x + threadIdx.x; i < E;
         i += gridDim.x * blockDim.x)
        atomicAdd(&deg[dst[i]], 1);
}

__global__ void make_inv_kernel(const int* __restrict__ deg, float* inv, int n) {
    for (int i = blockIdx.x * blockDim.x + threadIdx.x; i < n;
         i += gridDim.x * blockDim.x)
        inv[i] = 1.0f / (float)max(deg[i], 1);
}

// S[row][:] /= max(deg[row],1)
__global__ void norm_rows_kernel(float* S, const int* __restrict__ deg, int rows) {
    int idx = blockIdx.x * blockDim.x + threadIdx.x;
    int n = rows * DD;
    if (idx >= n) return;
    int r = idx / DD;
    S[idx] *= 1.0f / (float)max(deg[r], 1);
}

// ---------------------------------------------------------------------------
// Type encoders: out[row] = relu(x[row] @ W + b), 32 rows per block, 256 threads
// ---------------------------------------------------------------------------
template <int K>
__global__ void encode_kernel(const float* __restrict__ X,
                              const float* __restrict__ W,
                              const float* __restrict__ bias,
                              float* __restrict__ out, int M) {
    __shared__ float Ws[K * DD];
    __shared__ float Xs[32 * K];
    int tid = threadIdx.x;
    for (int i = tid; i < K * DD; i += 256) Ws[i] = W[i];
    int r0 = blockIdx.x * 32;
    int rows = min(32, M - r0);
    for (int i = tid; i < rows * K; i += 256) Xs[i] = X[(size_t)r0 * K + i];
    __syncthreads();
    int col = tid;
    float bv = bias[col];
    for (int row = 0; row < rows; row++) {
        float acc = 0.0f;
#pragma unroll
        for (int k = 0; k < K; k++) acc += Xs[row * K + k] * Ws[k * DD + col];
        out[(size_t)(r0 + row) * DD + col] = fmaxf(acc + bv, 0.0f);
    }
}

// ---------------------------------------------------------------------------
// fp32 SGEMM: C[M x 256] = A[M x 256] @ Bw[256 x 256] (+ bias | += C)
// 128x128 blocktile, BK=8, 8x8 per thread, 256 threads.
// ---------------------------------------------------------------------------
#define BM 128
#define BN 128
#define BK 8

__global__ void __launch_bounds__(256, 2)
gemm256_kernel(const float* __restrict__ A, const float* __restrict__ Bw,
               const float* __restrict__ bias, float* __restrict__ C,
               int M, int accum) {
    __shared__ float As[BK][BM];
    __shared__ float Bs[BK][BN];

    int tid = threadIdx.x;
    int rowBase = blockIdx.x * BM;
    int colBase = blockIdx.y * BN;
    int tx = tid & 15;        // 0..15
    int ty = tid >> 4;        // 0..15

    int aRow = tid >> 1;          // 0..127
    int aCol = (tid & 1) * 4;     // 0 or 4
    int bRow = tid >> 5;          // 0..7
    int bCol = (tid & 31) * 4;    // 0..124

    float acc[8][8];
#pragma unroll
    for (int i = 0; i < 8; i++)
#pragma unroll
        for (int j = 0; j < 8; j++) acc[i][j] = 0.0f;

    for (int k0 = 0; k0 < DD; k0 += BK) {
        float4 av = make_float4(0.f, 0.f, 0.f, 0.f);
        int ar = rowBase + aRow;
        if (ar < M)
            av = *(const float4*)(A + (size_t)ar * DD + k0 + aCol);
        As[aCol + 0][aRow] = av.x;
        As[aCol + 1][aRow] = av.y;
        As[aCol + 2][aRow] = av.z;
        As[aCol + 3][aRow] = av.w;

        float4 bv = *(const float4*)(Bw + (size_t)(k0 + bRow) * DD + colBase + bCol);
        *(float4*)(&Bs[bRow][bCol]) = bv;
        __syncthreads();

#pragma unroll
        for (int kk = 0; kk < BK; kk++) {
            float ra[8], rb[8];
#pragma unroll
            for (int i = 0; i < 8; i++) ra[i] = As[kk][ty * 8 + i];
#pragma unroll
            for (int j = 0; j < 8; j++) rb[j] = Bs[kk][tx * 8 + j];
#pragma unroll
            for (int i = 0; i < 8; i++)
#pragma unroll
                for (int j = 0; j < 8; j++) acc[i][j] += ra[i] * rb[j];
        }
        __syncthreads();
    }

#pragma unroll
    for (int i = 0; i < 8; i++) {
        int row = rowBase + ty * 8 + i;
        if (row >= M) continue;
#pragma unroll
        for (int j4 = 0; j4 < 8; j4 += 4) {
            int col = colBase + tx * 8 + j4;
            float4 v = make_float4(acc[i][j4], acc[i][j4 + 1],
                                   acc[i][j4 + 2], acc[i][j4 + 3]);
            float* cp = C + (size_t)row * DD + col;
            if (accum) {
                float4 o = *(const float4*)cp;
                v.x += o.x; v.y += o.y; v.z += o.z; v.w += o.w;
            } else if (bias) {
                v.x += bias[col];     v.y += bias[col + 1];
                v.z += bias[col + 2]; v.w += bias[col + 3];
            }
            *(float4*)cp = v;
        }
    }
}

// ---------------------------------------------------------------------------
// Edge scatter: out[dst[e]] += tab[src[e]] * (inv ? inv[dst[e]] : 1)
// one warp per edge; red.global.add.v4.f32 (sm_90+)
// ---------------------------------------------------------------------------
__device__ __forceinline__ void red_add_v4(float* addr, float4 v) {
    asm volatile("red.global.add.v4.f32 [%0], {%1,%2,%3,%4};"
                 :: "l"(addr), "f"(v.x), "f"(v.y), "f"(v.z), "f"(v.w)
                 : "memory");
}

__global__ void scatter_add_kernel(const float* __restrict__ tab,
                                   const int* __restrict__ src,
                                   const int* __restrict__ dst,
                                   const float* __restrict__ inv,
                                   float* __restrict__ out, int E) {
    int w = (blockIdx.x * blockDim.x + threadIdx.x) >> 5;
    int lane = threadIdx.x & 31;
    if (w >= E) return;
    int s = src[w];
    int d = dst[w];
    float sc = inv ? inv[d] : 1.0f;
    const float4* in4 = (const float4*)(tab + (size_t)s * DD);
    float4 a = in4[lane];
    float4 b = in4[lane + 32];
    a.x *= sc; a.y *= sc; a.z *= sc; a.w *= sc;
    b.x *= sc; b.y *= sc; b.z *= sc; b.w *= sc;
    float* ob = out + (size_t)d * DD;
    red_add_v4(ob + lane * 4, a);
    red_add_v4(ob + (lane + 32) * 4, b);
}

// ---------------------------------------------------------------------------
// Readout: out[row] = x[row] . W_out + b_out, warp per row
// ---------------------------------------------------------------------------
__global__ void readout_kernel(const float* __restrict__ X,
                               const float* __restrict__ Wout,
                               const float* __restrict__ bout,
                               float* __restrict__ out, int M) {
    int w = (blockIdx.x * blockDim.x + threadIdx.x) >> 5;
    int lane = threadIdx.x & 31;
    if (w >= M) return;
    const float4* x4 = (const float4*)(X + (size_t)w * DD);
    const float4* w4 = (const float4*)Wout;
    float4 a = x4[lane],     wa = w4[lane];
    float4 b = x4[lane + 32], wb = w4[lane + 32];
    float s = a.x * wa.x + a.y * wa.y + a.z * wa.z + a.w * wa.w
            + b.x * wb.x + b.y * wb.y + b.z * wb.z + b.w * wb.w;
#pragma unroll
    for (int off = 16; off > 0; off >>= 1)
        s += __shfl_down_sync(0xffffffffu, s, off);
    if (lane == 0) out[w] = s + bout[0];
}

// ---------------------------------------------------------------------------
// Launch
// ---------------------------------------------------------------------------
extern "C" void kernel_launch(void* const* d_in, const int* in_sizes, int n_in,
                              void* d_out, int out_size) {
    (void)in_sizes; (void)n_in; (void)out_size;

    const float* x_flight  = (const float*)d_in[0];
    const float* x_airport = (const float*)d_in[1];
    const float* x_carrier = (const float*)d_in[2];
    const float* W_f = (const float*)d_in[3];
    const float* b_f = (const float*)d_in[4];
    const float* W_a = (const float*)d_in[5];
    const float* b_a = (const float*)d_in[6];
    const float* W_c = (const float*)d_in[7];
    const float* b_c = (const float*)d_in[8];
    const float* basis0 = (const float*)d_in[9];
    const float* comp0  = (const float*)d_in[10];
    const float* root0  = (const float*)d_in[11];
    const float* bias0  = (const float*)d_in[12];
    const float* basis1 = (const float*)d_in[13];
    const float* comp1  = (const float*)d_in[14];
    const float* root1  = (const float*)d_in[15];
    const float* bias1  = (const float*)d_in[16];
    const float* W_out  = (const float*)d_in[17];
    const float* b_out  = (const float*)d_in[18];
    const int* src0 = (const int*)d_in[19];
    const int* dst0 = (const int*)d_in[20];
    const int* src1 = (const int*)d_in[21];
    const int* dst1 = (const int*)d_in[22];
    const int* src2 = (const int*)d_in[23];
    const int* dst2 = (const int*)d_in[24];
    const int* src3 = (const int*)d_in[25];
    const int* dst3 = (const int*)d_in[26];
    float* out_final = (float*)d_out;

    void *pA, *pB, *pW, *pY1, *pY3, *pS0, *pS2;
    void *pd0, *pd1, *pd2, *pd3, *pi1, *pi3;
    cudaGetSymbolAddress(&pA,  g_A);
    cudaGetSymbolAddress(&pB,  g_Bf);
    cudaGetSymbolAddress(&pW,  g_W);
    cudaGetSymbolAddress(&pY1, g_Y1);
    cudaGetSymbolAddress(&pY3, g_Y3);
    cudaGetSymbolAddress(&pS0, g_S0);
    cudaGetSymbolAddress(&pS2, g_S2);
    cudaGetSymbolAddress(&pd0, g_deg0);
    cudaGetSymbolAddress(&pd1, g_deg1);
    cudaGetSymbolAddress(&pd2, g_deg2);
    cudaGetSymbolAddress(&pd3, g_deg3);
    cudaGetSymbolAddress(&pi1, g_inv1);
    cudaGetSymbolAddress(&pi3, g_inv3);

    float* A  = (float*)pA;
    float* Bf = (float*)pB;
    float* W  = (float*)pW;         // [2][4][256*256]
    float* Y1 = (float*)pY1;
    float* Y3 = (float*)pY3;
    float* S0 = (float*)pS0;
    float* S2 = (float*)pS2;
    int* deg0 = (int*)pd0;
    int* deg1 = (int*)pd1;
    int* deg2 = (int*)pd2;
    int* deg3 = (int*)pd3;
    float* inv1 = (float*)pi1;
    float* inv3 = (float*)pi3;

    const size_t WSZ = (size_t)DD * DD;  // 65536
    float* W0 = W;                       // layer 0 relation weights
    float* W1 = W + DR * WSZ;            // layer 1 relation weights

    // 1. relation weights from basis decomposition (both layers)
    {
        int total = DR * DD * DD;
        int blocks = (total + 255) / 256;
        compute_W_kernel<<<blocks, 256>>>(basis0, comp0, W0);
        compute_W_kernel<<<blocks, 256>>>(basis1, comp1, W1);
    }

    // 2. encoders -> A
    encode_kernel<32><<<(DNF + 31) / 32, 256>>>(x_flight, W_f, b_f, A, DNF);
    encode_kernel<16><<<(DNA + 31) / 32, 256>>>(x_airport, W_a, b_a,
                                                A + (size_t)DNF * DD, DNA);
    encode_kernel<8><<<(DNC + 31) / 32, 256>>>(x_carrier, W_c, b_c,
                                               A + (size_t)(DNF + DNA) * DD, DNC);

    // 3. degrees + inverse degrees (shared across both layers)
    zero_i_kernel<<<64, 256>>>(deg0, DNA);
    zero_i_kernel<<<512, 256>>>(deg1, DNF);
    zero_i_kernel<<<64, 256>>>(deg2, DNC);
    zero_i_kernel<<<512, 256>>>(deg3, DNF);
    {
        int blocks = (DE + 255) / 256;
        count_deg_kernel<<<blocks, 256>>>(dst0, deg0, DE);
        count_deg_kernel<<<blocks, 256>>>(dst1, deg1, DE);
        count_deg_kernel<<<blocks, 256>>>(dst2, deg2, DE);
        count_deg_kernel<<<blocks, 256>>>(dst3, deg3, DE);
    }
    make_inv_kernel<<<(DNF + 255) / 256, 256>>>(deg1, inv1, DNF);
    make_inv_kernel<<<(DNF + 255) / 256, 256>>>(deg3, inv3, DNF);

    const int scatterBlocks = (DE * 32 + 255) / 256;
    dim3 gemmFullGrid((DNT + BM - 1) / BM, 2);
    dim3 gemmNFGrid((DNF + BM - 1) / BM, 2);
    dim3 gemmNAGrid((DNA + BM - 1) / BM, 2);
    dim3 gemmNCGrid((DNC + BM - 1) / BM, 2);

    // -------------------- Layer 0 --------------------
    // root/self transform over all nodes: Bf = A @ root0 + bias0
    gemm256_kernel<<<gemmFullGrid, 256>>>(A, root0, bias0, Bf, DNT, 0);

    // messages for airport->flight and carrier->flight (tiny GEMMs first)
    gemm256_kernel<<<gemmNAGrid, 256>>>(A + (size_t)DNF * DD, W0 + 1 * WSZ,
                                        nullptr, Y1, DNA, 0);
    gemm256_kernel<<<gemmNCGrid, 256>>>(A + (size_t)(DNF + DNA) * DD, W0 + 3 * WSZ,
                                        nullptr, Y3, DNC, 0);

    // rel0 / rel2 aggregates (aggregate raw x, GEMM after)
    zero_f_kernel<<<256, 256>>>(S0, DNA * DD);
    zero_f_kernel<<<64, 256>>>(S2, DNC * DD);
    scatter_add_kernel<<<scatterBlocks, 256>>>(A, src0, dst0, nullptr, S0, DE);
    scatter_add_kernel<<<scatterBlocks, 256>>>(A, src2, dst2, nullptr, S2, DE);
    norm_rows_kernel<<<(DNA * DD + 255) / 256, 256>>>(S0, deg0, DNA);
    norm_rows_kernel<<<(DNC * DD + 255) / 256, 256>>>(S2, deg2, DNC);
    gemm256_kernel<<<gemmNAGrid, 256>>>(S0, W0 + 0 * WSZ, nullptr,
                                        Bf + (size_t)DNF * DD, DNA, 1);
    gemm256_kernel<<<gemmNCGrid, 256>>>(S2, W0 + 2 * WSZ, nullptr,
                                        Bf + (size_t)(DNF + DNA) * DD, DNC, 1);

    // rel1 / rel3 scatter (pre-GEMMed messages) into flight rows of Bf
    scatter_add_kernel<<<scatterBlocks, 256>>>(Y1, src1, dst1, inv1, Bf, DE);
    scatter_add_kernel<<<scatterBlocks, 256>>>(Y3, src3, dst3, inv3, Bf, DE);

    relu_kernel<<<4096, 256>>>(Bf, DNT * DD);

    // -------------------- Layer 1 (flight rows only needed) --------------------
    gemm256_kernel<<<gemmNFGrid, 256>>>(Bf, root1, bias1, A, DNF, 0);
    gemm256_kernel<<<gemmNAGrid, 256>>>(Bf + (size_t)DNF * DD, W1 + 1 * WSZ,
                                        nullptr, Y1, DNA, 0);
    gemm256_kernel<<<gemmNCGrid, 256>>>(Bf + (size_t)(DNF + DNA) * DD, W1 + 3 * WSZ,
                                        nullptr, Y3, DNC, 0);
    scatter_add_kernel<<<scatterBlocks, 256>>>(Y1, src1, dst1, inv1, A, DE);
    scatter_add_kernel<<<scatterBlocks, 256>>>(Y3, src3, dst3, inv3, A, DE);
    relu_kernel<<<4096, 256>>>(A, DNF * DD);

    // -------------------- Readout --------------------
    readout_kernel<<<(DNF * 32 + 255) / 256, 256>>>(A, W_out, b_out,
                                                    out_final, DNF);
}

// round 5
// speedup vs baseline: 1.4207x; 1.4191x over previous
#include <cuda_runtime.h>
#include <cuda_bf16.h>
#include <cstdint>

#define DNF 100000
#define DNA 400
#define DNC 30
#define DNT (DNF + DNA + DNC)
#define DD  256
#define DE  250000
#define DB  3
#define DR  4

// ---------------- device scratch ----------------
__device__ __align__(16) float g_A[(size_t)DNT * DD];
__device__ __align__(16) float g_Bf[(size_t)DNT * DD];
__device__ __align__(16) float g_W[2][DR][DD * DD];
// bf16 split root weights, n-major: [layer][h/l][n*256+k]
__device__ __align__(16) __nv_bfloat16 g_Wsplit[2][2][DD * DD];
__device__ __align__(16) float g_Y1[DNA * DD];
__device__ __align__(16) float g_Y3[DNC * DD];
__device__ __align__(16) float g_S0[DNA * DD];
__device__ __align__(16) float g_S2[DNC * DD];
__device__ int   g_deg0[DNA];
__device__ int   g_deg1[DNF];
__device__ int   g_deg2[DNC];
__device__ int   g_deg3[DNF];
__device__ float g_inv1[DNF];
__device__ float g_inv3[DNF];
__device__ int   g_off0[DNA], g_cur0[DNA];
__device__ int   g_off2[DNC], g_cur2[DNC];
__device__ int   g_csr0[DE];
__device__ int   g_csr2[DE];

// ---------------- utility kernels ----------------
__global__ void zero_f_kernel(float* p, int n) {
    for (int i = blockIdx.x * blockDim.x + threadIdx.x; i < n; i += gridDim.x * blockDim.x)
        p[i] = 0.0f;
}
__global__ void zero_i_kernel(int* p, int n) {
    for (int i = blockIdx.x * blockDim.x + threadIdx.x; i < n; i += gridDim.x * blockDim.x)
        p[i] = 0;
}
__global__ void compute_W_kernel(const float* __restrict__ basis,
                                 const float* __restrict__ comp,
                                 float* __restrict__ Wout) {
    int idx = blockIdx.x * blockDim.x + threadIdx.x;
    if (idx >= DR * DD * DD) return;
    int r = idx / (DD * DD), io = idx % (DD * DD);
    float acc = 0.0f;
#pragma unroll
    for (int b = 0; b < DB; b++)
        acc += comp[r * DB + b] * basis[(size_t)b * DD * DD + io];
    Wout[idx] = acc;
}
// split root W[k][n] fp32 -> Wh/Wl bf16 stored n-major [n*256+k]
__global__ void prep_wsplit_kernel(const float* __restrict__ W,
                                   __nv_bfloat16* __restrict__ Wh,
                                   __nv_bfloat16* __restrict__ Wl) {
    int idx = blockIdx.x * blockDim.x + threadIdx.x;
    if (idx >= DD * DD) return;
    int n = idx >> 8, k = idx & 255;
    float v = W[k * 256 + n];
    __nv_bfloat16 hi = __float2bfloat16(v);
    __nv_bfloat16 lo = __float2bfloat16(v - __bfloat162float(hi));
    Wh[n * 256 + k] = hi;
    Wl[n * 256 + k] = lo;
}
__global__ void count_deg_kernel(const int* __restrict__ dst, int* deg, int E) {
    for (int i = blockIdx.x * blockDim.x + threadIdx.x; i < E; i += gridDim.x * blockDim.x)
        atomicAdd(&deg[dst[i]], 1);
}
__global__ void count_deg_smem_kernel(const int* __restrict__ dst, int* deg,
                                      int E, int n) {
    __shared__ int h[512];
    for (int i = threadIdx.x; i < n; i += blockDim.x) h[i] = 0;
    __syncthreads();
    for (int i = blockIdx.x * blockDim.x + threadIdx.x; i < E; i += gridDim.x * blockDim.x)
        atomicAdd(&h[dst[i]], 1);
    __syncthreads();
    for (int i = threadIdx.x; i < n; i += blockDim.x)
        if (h[i]) atomicAdd(&deg[i], h[i]);
}
__global__ void make_inv_kernel(const int* __restrict__ deg, float* inv, int n) {
    for (int i = blockIdx.x * blockDim.x + threadIdx.x; i < n; i += gridDim.x * blockDim.x)
        inv[i] = 1.0f / (float)max(deg[i], 1);
}
__global__ void scan_offsets_kernel(const int* __restrict__ deg, int* offs,
                                    int* cursor, int n) {
    __shared__ int tmp[512];
    int t = threadIdx.x;
    int v = (t < n) ? deg[t] : 0;
    tmp[t] = v;
    __syncthreads();
    for (int d = 1; d < 512; d <<= 1) {
        int add = (t >= d) ? tmp[t - d] : 0;
        __syncthreads();
        tmp[t] += add;
        __syncthreads();
    }
    if (t < n) { int e = tmp[t] - v; offs[t] = e; cursor[t] = e; }
}
__global__ void fill_csr_kernel(const int* __restrict__ src, const int* __restrict__ dst,
                                int* cursor, int* csr, int E) {
    for (int i = blockIdx.x * blockDim.x + threadIdx.x; i < E; i += gridDim.x * blockDim.x) {
        int p = atomicAdd(&cursor[dst[i]], 1);
        csr[p] = src[i];
    }
}
// S[row][col] += (1/deg) * sum_{src in csr chunk} tab[src][col]; S pre-zeroed
__global__ void gather_rel_kernel(const float* __restrict__ tab,
                                  const int* __restrict__ csr,
                                  const int* __restrict__ offs,
                                  const int* __restrict__ deg,
                                  float* __restrict__ S, int nrows, int split) {
    int w = (blockIdx.x * blockDim.x + threadIdx.x) >> 5;
    int lane = threadIdx.x & 31;
    if (w >= nrows * 8 * split) return;
    int row = w / (8 * split);
    int rr = w % (8 * split);
    int cg = rr & 7, chunk = rr >> 3;
    int col = cg * 32 + lane;
    int d = deg[row], beg = offs[row];
    int per = (d + split - 1) / split;
    int s0 = beg + chunk * per;
    int s1 = min(beg + d, s0 + per);
    if (s0 >= s1) return;
    float acc = 0.0f;
    int e = s0;
    for (; e + 4 <= s1; e += 4) {
        int i0 = csr[e], i1 = csr[e + 1], i2 = csr[e + 2], i3 = csr[e + 3];
        acc += (tab[(size_t)i0 * DD + col] + tab[(size_t)i1 * DD + col]) +
               (tab[(size_t)i2 * DD + col] + tab[(size_t)i3 * DD + col]);
    }
    for (; e < s1; e++) acc += tab[(size_t)csr[e] * DD + col];
    acc *= 1.0f / (float)max(d, 1);
    atomicAdd(&S[(size_t)row * DD + col], acc);
}

// flight encoder: out = relu(X @ W + b)
__global__ void encode32_kernel(const float* __restrict__ X, const float* __restrict__ W,
                                const float* __restrict__ bias, float* __restrict__ out,
                                int M) {
    __shared__ float Ws[32 * DD];
    __shared__ float Xs[32 * 32];
    int tid = threadIdx.x;
    for (int i = tid; i < 32 * DD; i += 256) Ws[i] = W[i];
    int r0 = blockIdx.x * 32;
    int rows = min(32, M - r0);
    for (int i = tid; i < rows * 32; i += 256) Xs[i] = X[(size_t)r0 * 32 + i];
    __syncthreads();
    int col = tid;
    float bv = bias[col];
    for (int row = 0; row < rows; row++) {
        float acc = 0.0f;
#pragma unroll
        for (int k = 0; k < 32; k++) acc += Xs[row * 32 + k] * Ws[k * DD + col];
        out[(size_t)(r0 + row) * DD + col] = fmaxf(acc + bv, 0.0f);
    }
}

// small-M GEMM: warp per (row, 32-col group). C[Mx256] = op(A[MxK]) @ W[Kx256]
__global__ void smallmm_kernel(const float* __restrict__ A, const float* __restrict__ W,
                               const float* __restrict__ bias, float* __restrict__ C,
                               int M, int K, int reluIn, int reluOut, int accum) {
    int w = (blockIdx.x * blockDim.x + threadIdx.x) >> 5;
    int lane = threadIdx.x & 31;
    int row = w >> 3, cg = w & 7;
    if (row >= M) return;
    int col = cg * 32 + lane;
    const float* a = A + (size_t)row * K;
    float acc = 0.0f;
#pragma unroll 4
    for (int k = 0; k < K; k += 4) {
        float4 av = *(const float4*)(a + k);
        if (reluIn) {
            av.x = fmaxf(av.x, 0.f); av.y = fmaxf(av.y, 0.f);
            av.z = fmaxf(av.z, 0.f); av.w = fmaxf(av.w, 0.f);
        }
        acc += av.x * W[(k + 0) * 256 + col] + av.y * W[(k + 1) * 256 + col] +
               av.z * W[(k + 2) * 256 + col] + av.w * W[(k + 3) * 256 + col];
    }
    float outv = acc + (bias ? bias[col] : 0.0f);
    float* cp = C + (size_t)row * 256 + col;
    if (accum) outv += *cp;
    if (reluOut) outv = fmaxf(outv, 0.0f);
    *cp = outv;
}

// ---------------------------------------------------------------------------
// bf16 split GEMM via mma.sync (m16n8k16, baseline ISA, works on sm_100):
// C[Mx256] = (relu?)A[Mx256] @ Wroot[256x256] + bias
// 3 terms: Ah@Wh + Al@Wh + Ah@Wl -> virtual K = 768, 24 k32-steps.
// Block 128x128, 8 warps (2x4), warp tile 64x32.
// ---------------------------------------------------------------------------
__device__ __forceinline__ uint32_t pack_bf16_hi(float f0, float f1) {
    return (uint32_t)__bfloat16_as_ushort(__float2bfloat16(f0)) |
           ((uint32_t)__bfloat16_as_ushort(__float2bfloat16(f1)) << 16);
}
__device__ __forceinline__ uint32_t pack_bf16_lo(float f0, float f1) {
    __nv_bfloat16 h0 = __float2bfloat16(f0);
    __nv_bfloat16 h1 = __float2bfloat16(f1);
    __nv_bfloat16 l0 = __float2bfloat16(f0 - __bfloat162float(h0));
    __nv_bfloat16 l1 = __float2bfloat16(f1 - __bfloat162float(h1));
    return (uint32_t)__bfloat16_as_ushort(l0) |
           ((uint32_t)__bfloat16_as_ushort(l1) << 16);
}
__device__ __forceinline__ void mma16816(float* c, const uint32_t* a,
                                         const uint32_t* b) {
    asm volatile(
        "mma.sync.aligned.m16n8k16.row.col.f32.bf16.bf16.f32 "
        "{%0,%1,%2,%3}, {%4,%5,%6,%7}, {%8,%9}, {%0,%1,%2,%3};"
        : "+f"(c[0]), "+f"(c[1]), "+f"(c[2]), "+f"(c[3])
        : "r"(a[0]), "r"(a[1]), "r"(a[2]), "r"(a[3]), "r"(b[0]), "r"(b[1]));
}

#define SPAD 18  // u32 row stride (36 bf16) -> conflict-free fragment loads

__global__ void __launch_bounds__(256)
mma_split_kernel(const float* __restrict__ A,
                 const __nv_bfloat16* __restrict__ Wh,
                 const __nv_bfloat16* __restrict__ Wl,
                 const float* __restrict__ bias, float* __restrict__ C,
                 int M, int reluA) {
    __shared__ uint32_t As[2][128 * SPAD];
    __shared__ uint32_t Bs[2][128 * SPAD];

    int tid = threadIdx.x;
    int lane = tid & 31, wid = tid >> 5;
    int warpM = wid >> 2;      // 0..1  (64 rows)
    int warpN = wid & 3;       // 0..3  (32 cols)
    int m0 = blockIdx.x * 128;
    int n0 = blockIdx.y * 128;

    const uint32_t* WhU = (const uint32_t*)Wh;
    const uint32_t* WlU = (const uint32_t*)Wl;

    float acc[4][4][4];
#pragma unroll
    for (int i = 0; i < 4; i++)
#pragma unroll
        for (int j = 0; j < 4; j++)
#pragma unroll
            for (int q = 0; q < 4; q++) acc[i][j][q] = 0.0f;

    float4 aReg[4];
    uint32_t bReg[8];

    // term t = s/8 (0:AhWh 1:AlWh 2:AhWl), kk = (s%8)*32
    auto loadTile = [&](int s) {
        int t = s >> 3, kk = (s & 7) << 5;
#pragma unroll
        for (int j = 0; j < 4; j++) {
            int id = j * 256 + tid;          // 0..1023 float4 slots
            int row = id >> 3, q = id & 7;
            int rg = m0 + row;
            float4 v = make_float4(0.f, 0.f, 0.f, 0.f);
            if (rg < M) v = *(const float4*)(A + (size_t)rg * 256 + kk + q * 4);
            aReg[j] = v;
        }
        const uint32_t* src = (t < 2) ? WhU : WlU;
#pragma unroll
        for (int j = 0; j < 8; j++) {
            int id = j * 256 + tid;          // 0..2047 u32 slots
            int n = id >> 4, c = id & 15;
            bReg[j] = src[(size_t)(n0 + n) * 128 + (kk >> 1) + c];
        }
    };

    auto storeTile = [&](int s, int buf) {
        int t = s >> 3;
        bool useLo = (t == 1);
#pragma unroll
        for (int j = 0; j < 4; j++) {
            int id = j * 256 + tid;
            int row = id >> 3, q = id & 7;
            float4 v = aReg[j];
            if (reluA) {
                v.x = fmaxf(v.x, 0.f); v.y = fmaxf(v.y, 0.f);
                v.z = fmaxf(v.z, 0.f); v.w = fmaxf(v.w, 0.f);
            }
            uint32_t p0, p1;
            if (useLo) {
                p0 = pack_bf16_lo(v.x, v.y);
                p1 = pack_bf16_lo(v.z, v.w);
            } else {
                p0 = pack_bf16_hi(v.x, v.y);
                p1 = pack_bf16_hi(v.z, v.w);
            }
            As[buf][row * SPAD + q * 2] = p0;
            As[buf][row * SPAD + q * 2 + 1] = p1;
        }
#pragma unroll
        for (int j = 0; j < 8; j++) {
            int id = j * 256 + tid;
            int n = id >> 4, c = id & 15;
            Bs[buf][n * SPAD + c] = bReg[j];
        }
    };

    auto mmaStep = [&](int buf) {
#pragma unroll
        for (int ks = 0; ks < 2; ks++) {
            int colk = ks * 8 + (lane & 3);
            uint32_t af[4][4];
            uint32_t bfr[4][2];
            int rbase = warpM * 64 + (lane >> 2);
#pragma unroll
            for (int mt = 0; mt < 4; mt++) {
                int r = rbase + mt * 16;
                af[mt][0] = As[buf][r * SPAD + colk];
                af[mt][1] = As[buf][(r + 8) * SPAD + colk];
                af[mt][2] = As[buf][r * SPAD + colk + 4];
                af[mt][3] = As[buf][(r + 8) * SPAD + colk + 4];
            }
            int nbase = warpN * 32 + (lane >> 2);
#pragma unroll
            for (int nt = 0; nt < 4; nt++) {
                int n = nbase + nt * 8;
                bfr[nt][0] = Bs[buf][n * SPAD + colk];
                bfr[nt][1] = Bs[buf][n * SPAD + colk + 4];
            }
#pragma unroll
            for (int mt = 0; mt < 4; mt++)
#pragma unroll
                for (int nt = 0; nt < 4; nt++)
                    mma16816(acc[mt][nt], af[mt], bfr[nt]);
        }
    };

    loadTile(0);
    for (int s = 0; s < 24; s++) {
        int buf = s & 1;
        storeTile(s, buf);
        __syncthreads();
        if (s < 23) loadTile(s + 1);
        mmaStep(buf);
    }

    // epilogue: acc layout c0,c1 -> row lane/4, cols (lane%4)*2,+1; c2,c3 -> row+8
#pragma unroll
    for (int mt = 0; mt < 4; mt++) {
        int r = m0 + warpM * 64 + mt * 16 + (lane >> 2);
#pragma unroll
        for (int nt = 0; nt < 4; nt++) {
            int c = n0 + warpN * 32 + nt * 8 + (lane & 3) * 2;
            float b0 = bias[c], b1 = bias[c + 1];
            if (r < M) {
                float2 v0 = make_float2(acc[mt][nt][0] + b0, acc[mt][nt][1] + b1);
                *(float2*)(C + (size_t)r * 256 + c) = v0;
            }
            if (r + 8 < M) {
                float2 v1 = make_float2(acc[mt][nt][2] + b0, acc[mt][nt][3] + b1);
                *(float2*)(C + (size_t)(r + 8) * 256 + c) = v1;
            }
        }
    }
}

// spread-dst scatter: out[dst[e]] += tab[src[e]] * inv[dst[e]]
__device__ __forceinline__ void red_add_v4(float* addr, float4 v) {
    asm volatile("red.global.add.v4.f32 [%0], {%1,%2,%3,%4};"
                 :: "l"(addr), "f"(v.x), "f"(v.y), "f"(v.z), "f"(v.w) : "memory");
}
__global__ void scatter_add_kernel(const float* __restrict__ tab,
                                   const int* __restrict__ src,
                                   const int* __restrict__ dst,
                                   const float* __restrict__ inv,
                                   float* __restrict__ out, int E) {
    int w = (blockIdx.x * blockDim.x + threadIdx.x) >> 5;
    int lane = threadIdx.x & 31;
    if (w >= E) return;
    int s = src[w], d = dst[w];
    float sc = inv[d];
    const float4* in4 = (const float4*)(tab + (size_t)s * DD);
    float4 a = in4[lane], b = in4[lane + 32];
    a.x *= sc; a.y *= sc; a.z *= sc; a.w *= sc;
    b.x *= sc; b.y *= sc; b.z *= sc; b.w *= sc;
    float* ob = out + (size_t)d * DD;
    red_add_v4(ob + lane * 4, a);
    red_add_v4(ob + (lane + 32) * 4, b);
}

// readout: out[row] = relu(x[row]) . W_out + b_out
__global__ void readout_kernel(const float* __restrict__ X, const float* __restrict__ Wout,
                               const float* __restrict__ bout, float* __restrict__ out,
                               int M) {
    int w = (blockIdx.x * blockDim.x + threadIdx.x) >> 5;
    int lane = threadIdx.x & 31;
    if (w >= M) return;
    const float4* x4 = (const float4*)(X + (size_t)w * DD);
    const float4* w4 = (const float4*)Wout;
    float4 a = x4[lane], wa = w4[lane];
    float4 b = x4[lane + 32], wb = w4[lane + 32];
    float s = fmaxf(a.x, 0.f) * wa.x + fmaxf(a.y, 0.f) * wa.y +
              fmaxf(a.z, 0.f) * wa.z + fmaxf(a.w, 0.f) * wa.w +
              fmaxf(b.x, 0.f) * wb.x + fmaxf(b.y, 0.f) * wb.y +
              fmaxf(b.z, 0.f) * wb.z + fmaxf(b.w, 0.f) * wb.w;
#pragma unroll
    for (int off = 16; off > 0; off >>= 1) s += __shfl_down_sync(0xffffffffu, s, off);
    if (lane == 0) out[w] = s + bout[0];
}

// ---------------- launch ----------------
extern "C" void kernel_launch(void* const* d_in, const int* in_sizes, int n_in,
                              void* d_out, int out_size) {
    (void)in_sizes; (void)n_in; (void)out_size;
    const float* x_flight  = (const float*)d_in[0];
    const float* x_airport = (const float*)d_in[1];
    const float* x_carrier = (const float*)d_in[2];
    const float* W_f = (const float*)d_in[3];
    const float* b_f = (const float*)d_in[4];
    const float* W_a = (const float*)d_in[5];
    const float* b_a = (const float*)d_in[6];
    const float* W_c = (const float*)d_in[7];
    const float* b_c = (const float*)d_in[8];
    const float* basis0 = (const float*)d_in[9];
    const float* comp0  = (const float*)d_in[10];
    const float* root0  = (const float*)d_in[11];
    const float* bias0  = (const float*)d_in[12];
    const float* basis1 = (const float*)d_in[13];
    const float* comp1  = (const float*)d_in[14];
    const float* root1  = (const float*)d_in[15];
    const float* bias1  = (const float*)d_in[16];
    const float* W_out  = (const float*)d_in[17];
    const float* b_out  = (const float*)d_in[18];
    const int* src0 = (const int*)d_in[19];
    const int* dst0 = (const int*)d_in[20];
    const int* src1 = (const int*)d_in[21];
    const int* dst1 = (const int*)d_in[22];
    const int* src2 = (const int*)d_in[23];
    const int* dst2 = (const int*)d_in[24];
    const int* src3 = (const int*)d_in[25];
    const int* dst3 = (const int*)d_in[26];
    float* out_final = (float*)d_out;

    void *pA, *pB, *pW, *pWs, *pY1, *pY3, *pS0, *pS2;
    void *pd0, *pd1, *pd2, *pd3, *pi1, *pi3, *po0, *pc0, *po2, *pc2, *pe0, *pe2;
    cudaGetSymbolAddress(&pA, g_A);       cudaGetSymbolAddress(&pB, g_Bf);
    cudaGetSymbolAddress(&pW, g_W);       cudaGetSymbolAddress(&pWs, g_Wsplit);
    cudaGetSymbolAddress(&pY1, g_Y1);     cudaGetSymbolAddress(&pY3, g_Y3);
    cudaGetSymbolAddress(&pS0, g_S0);     cudaGetSymbolAddress(&pS2, g_S2);
    cudaGetSymbolAddress(&pd0, g_deg0);   cudaGetSymbolAddress(&pd1, g_deg1);
    cudaGetSymbolAddress(&pd2, g_deg2);   cudaGetSymbolAddress(&pd3, g_deg3);
    cudaGetSymbolAddress(&pi1, g_inv1);   cudaGetSymbolAddress(&pi3, g_inv3);
    cudaGetSymbolAddress(&po0, g_off0);   cudaGetSymbolAddress(&pc0, g_cur0);
    cudaGetSymbolAddress(&po2, g_off2);   cudaGetSymbolAddress(&pc2, g_cur2);
    cudaGetSymbolAddress(&pe0, g_csr0);   cudaGetSymbolAddress(&pe2, g_csr2);

    float* A = (float*)pA;  float* Bf = (float*)pB;  float* W = (float*)pW;
    __nv_bfloat16* Ws = (__nv_bfloat16*)pWs;
    float* Y1 = (float*)pY1; float* Y3 = (float*)pY3;
    float* S0 = (float*)pS0; float* S2 = (float*)pS2;
    int* deg0 = (int*)pd0; int* deg1 = (int*)pd1;
    int* deg2 = (int*)pd2; int* deg3 = (int*)pd3;
    float* inv1 = (float*)pi1; float* inv3 = (float*)pi3;
    int* off0 = (int*)po0; int* cur0 = (int*)pc0;
    int* off2 = (int*)po2; int* cur2 = (int*)pc2;
    int* csr0 = (int*)pe0; int* csr2 = (int*)pe2;

    const size_t WSZ = (size_t)DD * DD;
    float* W0 = W;
    float* W1 = W + DR * WSZ;
    __nv_bfloat16* Wh0 = Ws;                 // [65536]
    __nv_bfloat16* Wl0 = Ws + WSZ;
    __nv_bfloat16* Wh1 = Ws + 2 * WSZ;
    __nv_bfloat16* Wl1 = Ws + 3 * WSZ;

    // weights
    {
        int blocks = (DR * DD * DD + 255) / 256;
        compute_W_kernel<<<blocks, 256>>>(basis0, comp0, W0);
        compute_W_kernel<<<blocks, 256>>>(basis1, comp1, W1);
        prep_wsplit_kernel<<<(DD * DD + 255) / 256, 256>>>(root0, Wh0, Wl0);
        prep_wsplit_kernel<<<(DD * DD + 255) / 256, 256>>>(root1, Wh1, Wl1);
    }
    // encoders
    encode32_kernel<<<(DNF + 31) / 32, 256>>>(x_flight, W_f, b_f, A, DNF);
    smallmm_kernel<<<DNA, 256>>>(x_airport, W_a, b_a, A + (size_t)DNF * DD,
                                 DNA, 16, 0, 1, 0);
    smallmm_kernel<<<DNC, 256>>>(x_carrier, W_c, b_c, A + (size_t)(DNF + DNA) * DD,
                                 DNC, 8, 0, 1, 0);
    // degrees
    zero_i_kernel<<<2, 256>>>(deg0, DNA);
    zero_i_kernel<<<392, 256>>>(deg1, DNF);
    zero_i_kernel<<<1, 256>>>(deg2, DNC);
    zero_i_kernel<<<392, 256>>>(deg3, DNF);
    count_deg_smem_kernel<<<148, 256>>>(dst0, deg0, DE, DNA);
    count_deg_kernel<<<(DE + 255) / 256, 256>>>(dst1, deg1, DE);
    count_deg_smem_kernel<<<148, 256>>>(dst2, deg2, DE, DNC);
    count_deg_kernel<<<(DE + 255) / 256, 256>>>(dst3, deg3, DE);
    make_inv_kernel<<<(DNF + 255) / 256, 256>>>(deg1, inv1, DNF);
    make_inv_kernel<<<(DNF + 255) / 256, 256>>>(deg3, inv3, DNF);
    // CSR for rel0/rel2
    scan_offsets_kernel<<<1, 512>>>(deg0, off0, cur0, DNA);
    fill_csr_kernel<<<(DE + 255) / 256, 256>>>(src0, dst0, cur0, csr0, DE);
    scan_offsets_kernel<<<1, 512>>>(deg2, off2, cur2, DNC);
    fill_csr_kernel<<<(DE + 255) / 256, 256>>>(src2, dst2, cur2, csr2, DE);

    const int scatterBlocks = (DE * 32 + 255) / 256;
    dim3 gFull((DNT + 127) / 128, 2);
    dim3 gNF((DNF + 127) / 128, 2);

    // ---------- layer 0 ----------
    mma_split_kernel<<<gFull, 256>>>(A, Wh0, Wl0, bias0, Bf, DNT, 0);
    smallmm_kernel<<<DNA, 256>>>(A + (size_t)DNF * DD, W0 + 1 * WSZ, nullptr, Y1,
                                 DNA, 256, 0, 0, 0);
    smallmm_kernel<<<DNC, 256>>>(A + (size_t)(DNF + DNA) * DD, W0 + 3 * WSZ, nullptr, Y3,
                                 DNC, 256, 0, 0, 0);
    zero_f_kernel<<<256, 256>>>(S0, DNA * DD);
    zero_f_kernel<<<32, 256>>>(S2, DNC * DD);
    gather_rel_kernel<<<(DNA * 8 * 8 * 32 + 255) / 256, 256>>>(A, csr0, off0, deg0,
                                                               S0, DNA, 8);
    gather_rel_kernel<<<(DNC * 8 * 64 * 32 + 255) / 256, 256>>>(A, csr2, off2, deg2,
                                                                S2, DNC, 64);
    smallmm_kernel<<<DNA, 256>>>(S0, W0 + 0 * WSZ, nullptr, Bf + (size_t)DNF * DD,
                                 DNA, 256, 0, 0, 1);
    smallmm_kernel<<<DNC, 256>>>(S2, W0 + 2 * WSZ, nullptr, Bf + (size_t)(DNF + DNA) * DD,
                                 DNC, 256, 0, 0, 1);
    scatter_add_kernel<<<scatterBlocks, 256>>>(Y1, src1, dst1, inv1, Bf, DE);
    scatter_add_kernel<<<scatterBlocks, 256>>>(Y3, src3, dst3, inv3, Bf, DE);

    // ---------- layer 1 (flight rows only; relu fused into consumers) ----------
    mma_split_kernel<<<gNF, 256>>>(Bf, Wh1, Wl1, bias1, A, DNF, 1);
    smallmm_kernel<<<DNA, 256>>>(Bf + (size_t)DNF * DD, W1 + 1 * WSZ, nullptr, Y1,
                                 DNA, 256, 1, 0, 0);
    smallmm_kernel<<<DNC, 256>>>(Bf + (size_t)(DNF + DNA) * DD, W1 + 3 * WSZ, nullptr, Y3,
                                 DNC, 256, 1, 0, 0);
    scatter_add_kernel<<<scatterBlocks, 256>>>(Y1, src1, dst1, inv1, A, DE);
    scatter_add_kernel<<<scatterBlocks, 256>>>(Y3, src3, dst3, inv3, A, DE);

    // readout (relu fused)
    readout_kernel<<<(DNF * 32 + 255) / 256, 256>>>(A, W_out, b_out, out_final, DNF);
}